// round 9
// baseline (speedup 1.0000x reference)
#include <cuda_runtime.h>
#include <cuda_bf16.h>
#include <cstdint>

// ---------------------------------------------------------------------------
// T5RelativeAttention  (B=32, N=577, DIM=768, H=12, Dh=64)
// Round 8: mma.sync bf16x3 GEMMs + flash attention. Fixed the attention smem
// layout: row stride 72 bf16 (144B) for 64-wide tiles (round 6/7 used the
// GEMM's 40 and overflowed shared memory).
// ---------------------------------------------------------------------------

using u64 = unsigned long long;

constexpr int B_   = 32;
constexpr int H_   = 12;
constexpr int N_   = 577;
constexpr int NP_  = 576;
constexpr int D_   = 768;
constexpr int DH_  = 64;
constexpr int NRELC = 2209;
constexpr int BPAD = 640;                 // bias column stride
constexpr int IPADR = 656;                // bias row count (padded)
constexpr int MR   = B_ * N_;             // 18464
constexpr int JP   = 640;                 // padded key dim for Vt

#define CDIV(a,b) (((a)+(b)-1)/(b))

__device__ float g_v[(size_t)B_*H_*N_*DH_];
__device__ float g_bias[(size_t)H_*IPADR*BPAD];
// bf16 hi/lo splits
__device__ __nv_bfloat16 g_x0[(size_t)MR*D_],   g_x1[(size_t)MR*D_];
__device__ __nv_bfloat16 g_w0[(size_t)3*D_*D_], g_w1[(size_t)3*D_*D_];
__device__ __nv_bfloat16 g_p0[(size_t)D_*D_],   g_p1[(size_t)D_*D_];
__device__ __nv_bfloat16 g_ao0[(size_t)MR*D_],  g_ao1[(size_t)MR*D_];
__device__ __nv_bfloat16 g_q0[(size_t)B_*H_*N_*DH_], g_q1[(size_t)B_*H_*N_*DH_];
__device__ __nv_bfloat16 g_k0[(size_t)B_*H_*N_*DH_], g_k1[(size_t)B_*H_*N_*DH_];
__device__ __nv_bfloat16 g_vt0[(size_t)B_*H_*DH_*JP], g_vt1[(size_t)B_*H_*DH_*JP];

// ---------------- mma.sync / cp.async helpers -------------------------------
__device__ __forceinline__ void mma16816(float* d, const uint32_t* a, const uint32_t* b) {
    asm volatile(
        "mma.sync.aligned.m16n8k16.row.col.f32.bf16.bf16.f32 "
        "{%0,%1,%2,%3},{%4,%5,%6,%7},{%8,%9},{%0,%1,%2,%3};"
        : "+f"(d[0]), "+f"(d[1]), "+f"(d[2]), "+f"(d[3])
        : "r"(a[0]), "r"(a[1]), "r"(a[2]), "r"(a[3]), "r"(b[0]), "r"(b[1]));
}
__device__ __forceinline__ uint32_t s2u(const void* p) {
    uint32_t a;
    asm("{ .reg .u64 t; cvta.to.shared.u64 t, %1; cvt.u32.u64 %0, t; }" : "=r"(a) : "l"(p));
    return a;
}
__device__ __forceinline__ void cpa16(uint32_t dst, const void* src, int srcbytes) {
    asm volatile("cp.async.cg.shared.global [%0], [%1], 16, %2;"
                 :: "r"(dst), "l"(src), "r"(srcbytes));
}
__device__ __forceinline__ void cpa_commit() {
    asm volatile("cp.async.commit_group;" ::: "memory");
}
template<int N>
__device__ __forceinline__ void cpa_wait() {
    asm volatile("cp.async.wait_group %0;" :: "n"(N) : "memory");
}
// split-pack: hi = bf16x2(x,y) (x in low half), lo = residual pair
__device__ __forceinline__ void pksplit(float x, float y, uint32_t& hi, uint32_t& lo) {
    __nv_bfloat162 h = __floats2bfloat162_rn(x, y);
    float hx = __bfloat162float(h.x), hy = __bfloat162float(h.y);
    __nv_bfloat162 l = __floats2bfloat162_rn(x - hx, y - hy);
    hi = *(uint32_t*)&h; lo = *(uint32_t*)&l;
}

// ---------------------------------------------------------------------------
// K0: bias table (12 x 656 x 640, zero padded)
// ---------------------------------------------------------------------------
__global__ void bias_build(const float* __restrict__ b1, const float* __restrict__ b2,
                           const float* __restrict__ b3, const int* __restrict__ map) {
    int idx = blockIdx.x * blockDim.x + threadIdx.x;
    constexpr int TOT = H_ * IPADR * BPAD;
    if (idx >= TOT) return;
    int h = idx / (IPADR * BPAD);
    int r = idx - h * (IPADR * BPAD);
    int i = r / BPAD;
    int j = r - i * BPAD;
    float v = 0.f;
    if (i < N_ && j < N_) {
        if (i == NP_)      v = b1[h * N_ + j];
        else if (j == 0)   v = b2[h * NP_ + i];
        else               v = b3[h * NRELC + map[i * NP_ + (j - 1)]];
    }
    g_bias[idx] = v;
}

// ---------------------------------------------------------------------------
// K_split: fp32 -> (hi, lo) bf16.
// ---------------------------------------------------------------------------
template<int SRC>
__global__ void split_k(const float* __restrict__ src) {
    __nv_bfloat16 *hi, *lo; size_t n;
    if (SRC == 0)      { hi = g_x0; lo = g_x1; n = (size_t)MR * D_; }
    else if (SRC == 1) { hi = g_w0; lo = g_w1; n = (size_t)3 * D_ * D_; }
    else               { hi = g_p0; lo = g_p1; n = (size_t)D_ * D_; }
    size_t i = (size_t)blockIdx.x * blockDim.x + threadIdx.x;
    if (i * 4 >= n) return;
    float4 v = *(const float4*)(src + i * 4);
    float vv[4] = {v.x, v.y, v.z, v.w};
    __nv_bfloat16 hb[4], lb[4];
    #pragma unroll
    for (int j = 0; j < 4; j++) {
        hb[j] = __float2bfloat16(vv[j]);
        lb[j] = __float2bfloat16(vv[j] - __bfloat162float(hb[j]));
    }
    *(uint2*)(hi + i * 4) = *(uint2*)hb;
    *(uint2*)(lo + i * 4) = *(uint2*)lb;
}

// ---------------------------------------------------------------------------
// mma.sync GEMM: 128x128 CTA tile, BK=32, 8 warps (2x4), warp tile 64x32.
// (unchanged from round 5 — proven passing)
// ---------------------------------------------------------------------------
constexpr int APAD = 40;                       // bf16 row stride (80B), BK=32 rows
constexpr int MATB = 128 * APAD * 2;           // 10240 bytes per matrix
constexpr int BUFB = 4 * MATB;                 // 40960 bytes per buffer
constexpr int GEMM_SMEM = 2 * BUFB;            // 81920

template<int WHICH>
__global__ void __launch_bounds__(256, 1)
gemm_mma(const float* __restrict__ pbias, float* __restrict__ out) {
    extern __shared__ char sm[];
    const uint32_t sb = s2u(sm);
    const int t = threadIdx.x;
    const int lane = t & 31, wid = t >> 5;
    const int wm = wid >> 2, wn = wid & 3;
    const int m0 = blockIdx.y * 128;
    const int c0 = blockIdx.x * 128;

    const __nv_bfloat16 *A0g, *A1g, *B0g, *B1g;
    if (WHICH == 0) { A0g = g_x0;  A1g = g_x1;  B0g = g_w0; B1g = g_w1; }
    else            { A0g = g_ao0; A1g = g_ao1; B0g = g_p0; B1g = g_p1; }

    const int mrow = t >> 2;
    const int kc   = (t & 3) * 8;
    const bool av0 = (m0 + mrow) < MR;
    const bool av1 = (m0 + mrow + 64) < MR;
    const int arow0 = av0 ? (m0 + mrow) : (MR - 1);
    const int arow1 = av1 ? (m0 + mrow + 64) : (MR - 1);
    const uint32_t soff0 = (uint32_t)(mrow * 80 + kc * 2);
    const uint32_t soff1 = (uint32_t)((mrow + 64) * 80 + kc * 2);

    float acc[4][4][4];
    #pragma unroll
    for (int i = 0; i < 4; i++)
        #pragma unroll
        for (int j = 0; j < 4; j++)
            #pragma unroll
            for (int q = 0; q < 4; q++) acc[i][j][q] = 0.f;

    auto issue = [&](int buf, int kt) {
        const int ko = kt * 32 + kc;
        const uint32_t bs = sb + buf * BUFB;
        size_t a0 = (size_t)arow0 * D_ + ko;
        size_t a1 = (size_t)arow1 * D_ + ko;
        size_t b0 = (size_t)(c0 + mrow) * D_ + ko;
        size_t b1 = (size_t)(c0 + mrow + 64) * D_ + ko;
        cpa16(bs + soff0,            A0g + a0, av0 ? 16 : 0);
        cpa16(bs + soff1,            A0g + a1, av1 ? 16 : 0);
        cpa16(bs + MATB + soff0,     A1g + a0, av0 ? 16 : 0);
        cpa16(bs + MATB + soff1,     A1g + a1, av1 ? 16 : 0);
        cpa16(bs + 2*MATB + soff0,   B0g + b0, 16);
        cpa16(bs + 2*MATB + soff1,   B0g + b1, 16);
        cpa16(bs + 3*MATB + soff0,   B1g + b0, 16);
        cpa16(bs + 3*MATB + soff1,   B1g + b1, 16);
    };

    issue(0, 0);
    cpa_commit();

    const int ar = wm * 64 + (lane >> 2);
    const int br = wn * 32 + (lane >> 2);
    const int fc = (lane & 3) * 2;

    constexpr int NK = 24;
    for (int kt = 0; kt < NK; kt++) {
        const int buf = kt & 1;
        if (kt + 1 < NK) {
            issue(buf ^ 1, kt + 1);
            cpa_commit();
            cpa_wait<1>();
        } else {
            cpa_wait<0>();
        }
        __syncthreads();

        const __nv_bfloat16* sA0 = (const __nv_bfloat16*)(sm + buf * BUFB);
        const __nv_bfloat16* sA1 = (const __nv_bfloat16*)(sm + buf * BUFB + MATB);
        const __nv_bfloat16* sB0 = (const __nv_bfloat16*)(sm + buf * BUFB + 2*MATB);
        const __nv_bfloat16* sB1 = (const __nv_bfloat16*)(sm + buf * BUFB + 3*MATB);

        #pragma unroll
        for (int ks = 0; ks < 2; ks++) {
            const int kb = ks * 16 + fc;
            uint32_t ah[4][4], al[4][4], bh[4][2], bl[4][2];
            #pragma unroll
            for (int am = 0; am < 4; am++) {
                int base = (ar + am * 16) * APAD + kb;
                ah[am][0] = *(const uint32_t*)&sA0[base];
                ah[am][1] = *(const uint32_t*)&sA0[base + 8 * APAD];
                ah[am][2] = *(const uint32_t*)&sA0[base + 8];
                ah[am][3] = *(const uint32_t*)&sA0[base + 8 * APAD + 8];
                al[am][0] = *(const uint32_t*)&sA1[base];
                al[am][1] = *(const uint32_t*)&sA1[base + 8 * APAD];
                al[am][2] = *(const uint32_t*)&sA1[base + 8];
                al[am][3] = *(const uint32_t*)&sA1[base + 8 * APAD + 8];
            }
            #pragma unroll
            for (int an = 0; an < 4; an++) {
                int base = (br + an * 8) * APAD + kb;
                bh[an][0] = *(const uint32_t*)&sB0[base];
                bh[an][1] = *(const uint32_t*)&sB0[base + 8];
                bl[an][0] = *(const uint32_t*)&sB1[base];
                bl[an][1] = *(const uint32_t*)&sB1[base + 8];
            }
            #pragma unroll
            for (int am = 0; am < 4; am++)
                #pragma unroll
                for (int an = 0; an < 4; an++) {
                    mma16816(acc[am][an], ah[am], bh[an]);
                    mma16816(acc[am][an], ah[am], bl[an]);
                    mma16816(acc[am][an], al[am], bh[an]);
                }
        }
        __syncthreads();
    }

    // ---------------- epilogue ----------------------------------------------
    #pragma unroll
    for (int am = 0; am < 4; am++) {
        #pragma unroll
        for (int an = 0; an < 4; an++) {
            int cc = wn * 32 + an * 8 + (lane & 3) * 2;
            #pragma unroll
            for (int rr = 0; rr < 2; rr++) {
                int r = m0 + wm * 64 + am * 16 + (lane >> 2) + rr * 8;
                if (r >= MR) continue;
                float vx = acc[am][an][rr*2], vy = acc[am][an][rr*2+1];
                if (WHICH == 0) {
                    const int s  = c0 / D_;
                    const int w  = (c0 - s * D_) + cc;
                    const int hh = w >> 6, d = w & 63;
                    int bb = r / N_, n = r - bb * N_;
                    size_t off = (((size_t)(bb * H_ + hh)) * N_ + n) * DH_ + d;
                    if (s == 2) {
                        *(float2*)(g_v + off) = make_float2(vx, vy);
                    } else {
                        if (s == 0) { vx *= 0.125f; vy *= 0.125f; }
                        uint32_t hi, lo;
                        pksplit(vx, vy, hi, lo);
                        __nv_bfloat16* dh = (s == 0) ? g_q0 : g_k0;
                        __nv_bfloat16* dl = (s == 0) ? g_q1 : g_k1;
                        *(uint32_t*)(dh + off) = hi;
                        *(uint32_t*)(dl + off) = lo;
                    }
                } else {
                    float2 bv = *(const float2*)(pbias + c0 + cc);
                    *(float2*)(out + (size_t)r * D_ + c0 + cc) =
                        make_float2(vx + bv.x, vy + bv.y);
                }
            }
        }
    }
}

// ---------------------------------------------------------------------------
// V transpose: g_v [bh][j][d] fp32 -> g_vt0/1 [bh][d][JP] bf16 hi/lo.
// ---------------------------------------------------------------------------
__global__ void __launch_bounds__(256) vtrans() {
    __shared__ float ts[64][65];
    const int bh = blockIdx.y;
    const int j0 = blockIdx.x * 64;
    const int t  = threadIdx.x;
    const int d  = t & 63, jb = t >> 6;
    #pragma unroll
    for (int i = 0; i < 16; i++) {
        int j = jb * 16 + i;
        int gj = j0 + j;
        ts[j][d] = (gj < N_) ? g_v[((size_t)bh * N_ + gj) * DH_ + d] : 0.f;
    }
    __syncthreads();
    const int jp = t & 31, db = t >> 5;
    #pragma unroll
    for (int i = 0; i < 8; i++) {
        int d2 = db * 8 + i;
        float x0 = ts[2*jp][d2], x1 = ts[2*jp+1][d2];
        uint32_t hi, lo;
        pksplit(x0, x1, hi, lo);
        size_t off = ((size_t)bh * DH_ + d2) * JP + j0 + 2 * jp;
        *(uint32_t*)(g_vt0 + off) = hi;
        *(uint32_t*)(g_vt1 + off) = lo;
    }
}

// ---------------------------------------------------------------------------
// K2: tensor-core flash attention. 128 threads = 4 warps, warp owns 16 q-rows.
// smem: rows of 64 bf16 + 8 pad = 72 elems (144B).
//   Qh @0, Ql @9216; KV buf b @18432+b*36864: Kh +0, Kl +9216, Vh +18432, Vl +27648
// ---------------------------------------------------------------------------
constexpr int ATP   = 72;                      // bf16 row stride (144B)
constexpr int AMTB  = 64 * ATP * 2;            // 9216 bytes per matrix
constexpr int AKVB  = 4 * AMTB;                // 36864 per KV buffer
constexpr int ATT_SMEM = 2 * AMTB + 2 * AKVB;  // 92160

__global__ void __launch_bounds__(128, 1) attn_mma() {
    extern __shared__ char sm[];
    const uint32_t sb = s2u(sm);
    const int t = threadIdx.x, lane = t & 31, wid = t >> 5;
    const int gid = lane >> 2, tg = lane & 3;
    const int bh = blockIdx.y, h = bh % H_, b = bh / H_;
    const int i0 = blockIdx.x * 64;

    const size_t kvbase = (size_t)bh * N_ * DH_;
    const size_t vtbase = (size_t)bh * DH_ * JP;

    const int lrow = t >> 1;                   // 0..63
    const int lkc  = (t & 1) * 32;             // element offset in row

    // Q load (once)
    {
        bool v = (i0 + lrow) < N_;
        int qrow = v ? (i0 + lrow) : (N_ - 1);
        size_t g = kvbase + (size_t)qrow * DH_ + lkc;
        uint32_t s0 = sb + lrow * 144 + lkc * 2;
        #pragma unroll
        for (int i = 0; i < 4; i++) {
            cpa16(s0 + i * 16,        g_q0 + g + i * 8, v ? 16 : 0);
            cpa16(s0 + AMTB + i * 16, g_q1 + g + i * 8, v ? 16 : 0);
        }
    }
    cpa_commit();

    auto issueKV = [&](int buf, int jt) {
        int j0 = jt * 64;
        bool v = (j0 + lrow) < N_;
        int krow = v ? (j0 + lrow) : (N_ - 1);
        size_t gk = kvbase + (size_t)krow * DH_ + lkc;
        size_t gv = vtbase + (size_t)lrow * JP + j0 + lkc;
        uint32_t s0 = sb + 2 * AMTB + buf * AKVB + lrow * 144 + lkc * 2;
        #pragma unroll
        for (int i = 0; i < 4; i++) {
            cpa16(s0 + i * 16,            g_k0  + gk + i * 8, v ? 16 : 0);
            cpa16(s0 + AMTB + i * 16,     g_k1  + gk + i * 8, v ? 16 : 0);
            cpa16(s0 + 2 * AMTB + i * 16, g_vt0 + gv + i * 8, 16);
            cpa16(s0 + 3 * AMTB + i * 16, g_vt1 + gv + i * 8, 16);
        }
    };
    issueKV(0, 0);
    cpa_commit();

    const int war = wid * 16 + gid;            // local q row (0..63)
    float m0r = -1e30f, m1r = -1e30f, l0 = 0.f, l1 = 0.f;
    float o[8][4];
    #pragma unroll
    for (int a = 0; a < 8; a++)
        #pragma unroll
        for (int q = 0; q < 4; q++) o[a][q] = 0.f;

    const __nv_bfloat16* SQh = (const __nv_bfloat16*)sm;
    const __nv_bfloat16* SQl = SQh + 64 * ATP;

    for (int kt = 0; kt < 10; kt++) {
        const int buf = kt & 1;
        if (kt < 9) { issueKV(buf ^ 1, kt + 1); cpa_commit(); cpa_wait<1>(); }
        else        { cpa_wait<0>(); }
        __syncthreads();

        const int j0 = kt * 64;
        const __nv_bfloat16* SKh = (const __nv_bfloat16*)(sm + 2 * AMTB + buf * AKVB);
        const __nv_bfloat16* SKl = SKh + 64 * ATP;
        const __nv_bfloat16* SVh = SKh + 2 * 64 * ATP;
        const __nv_bfloat16* SVl = SKh + 3 * 64 * ATP;

        // bias fragments (rows padded to IPADR=656 so i0+war+8 <= 647 is safe)
        float2 bfr[8][2];
        {
            size_t r0 = ((size_t)h * IPADR + i0 + war) * BPAD + j0 + tg * 2;
            size_t r1 = r0 + 8 * BPAD;
            #pragma unroll
            for (int a = 0; a < 8; a++) {
                bfr[a][0] = *(const float2*)(g_bias + r0 + a * 8);
                bfr[a][1] = *(const float2*)(g_bias + r1 + a * 8);
            }
        }

        // S = Q K^T (bf16x3)
        float s[8][4];
        #pragma unroll
        for (int a = 0; a < 8; a++)
            #pragma unroll
            for (int q = 0; q < 4; q++) s[a][q] = 0.f;

        #pragma unroll
        for (int t4 = 0; t4 < 4; t4++) {
            const int kb = t4 * 16 + tg * 2;
            uint32_t qh[4], ql[4];
            int ab = war * ATP + kb;
            qh[0] = *(const uint32_t*)&SQh[ab];
            qh[1] = *(const uint32_t*)&SQh[ab + 8 * ATP];
            qh[2] = *(const uint32_t*)&SQh[ab + 8];
            qh[3] = *(const uint32_t*)&SQh[ab + 8 * ATP + 8];
            ql[0] = *(const uint32_t*)&SQl[ab];
            ql[1] = *(const uint32_t*)&SQl[ab + 8 * ATP];
            ql[2] = *(const uint32_t*)&SQl[ab + 8];
            ql[3] = *(const uint32_t*)&SQl[ab + 8 * ATP + 8];
            #pragma unroll
            for (int a = 0; a < 8; a++) {
                int bb = (a * 8 + gid) * ATP + kb;
                uint32_t kh[2] = {*(const uint32_t*)&SKh[bb], *(const uint32_t*)&SKh[bb + 8]};
                uint32_t kl[2] = {*(const uint32_t*)&SKl[bb], *(const uint32_t*)&SKl[bb + 8]};
                mma16816(s[a], qh, kh);
                mma16816(s[a], qh, kl);
                mma16816(s[a], ql, kh);
            }
        }

        // + bias, mask invalid keys (only last tile)
        #pragma unroll
        for (int a = 0; a < 8; a++) {
            s[a][0] += bfr[a][0].x; s[a][1] += bfr[a][0].y;
            s[a][2] += bfr[a][1].x; s[a][3] += bfr[a][1].y;
        }
        if (j0 + 64 > N_) {
            #pragma unroll
            for (int a = 0; a < 8; a++) {
                int jc = j0 + a * 8 + tg * 2;
                if (jc >= N_)     { s[a][0] = -1e30f; s[a][2] = -1e30f; }
                if (jc + 1 >= N_) { s[a][1] = -1e30f; s[a][3] = -1e30f; }
            }
        }

        // online softmax (rows r and r+8)
        float mx0 = -1e30f, mx1 = -1e30f;
        #pragma unroll
        for (int a = 0; a < 8; a++) {
            mx0 = fmaxf(mx0, fmaxf(s[a][0], s[a][1]));
            mx1 = fmaxf(mx1, fmaxf(s[a][2], s[a][3]));
        }
        mx0 = fmaxf(mx0, __shfl_xor_sync(0xffffffffu, mx0, 1));
        mx0 = fmaxf(mx0, __shfl_xor_sync(0xffffffffu, mx0, 2));
        mx1 = fmaxf(mx1, __shfl_xor_sync(0xffffffffu, mx1, 1));
        mx1 = fmaxf(mx1, __shfl_xor_sync(0xffffffffu, mx1, 2));
        float mn0 = fmaxf(m0r, mx0), mn1 = fmaxf(m1r, mx1);
        float c0f = __expf(m0r - mn0), c1f = __expf(m1r - mn1);
        m0r = mn0; m1r = mn1;
        float rs0 = 0.f, rs1 = 0.f;
        #pragma unroll
        for (int a = 0; a < 8; a++) {
            s[a][0] = __expf(s[a][0] - mn0);
            s[a][1] = __expf(s[a][1] - mn0);
            s[a][2] = __expf(s[a][2] - mn1);
            s[a][3] = __expf(s[a][3] - mn1);
            rs0 += s[a][0] + s[a][1];
            rs1 += s[a][2] + s[a][3];
        }
        rs0 += __shfl_xor_sync(0xffffffffu, rs0, 1);
        rs0 += __shfl_xor_sync(0xffffffffu, rs0, 2);
        rs1 += __shfl_xor_sync(0xffffffffu, rs1, 1);
        rs1 += __shfl_xor_sync(0xffffffffu, rs1, 2);
        l0 = l0 * c0f + rs0;
        l1 = l1 * c1f + rs1;
        #pragma unroll
        for (int a = 0; a < 8; a++) {
            o[a][0] *= c0f; o[a][1] *= c0f;
            o[a][2] *= c1f; o[a][3] *= c1f;
        }

        // O += P V  (P repacked reg->reg into A-frags, bf16x3)
        #pragma unroll
        for (int t4 = 0; t4 < 4; t4++) {
            uint32_t ah[4], al[4];
            pksplit(s[2*t4][0],   s[2*t4][1],   ah[0], al[0]);
            pksplit(s[2*t4][2],   s[2*t4][3],   ah[1], al[1]);
            pksplit(s[2*t4+1][0], s[2*t4+1][1], ah[2], al[2]);
            pksplit(s[2*t4+1][2], s[2*t4+1][3], ah[3], al[3]);
            const int kb = t4 * 16 + tg * 2;
            #pragma unroll
            for (int a = 0; a < 8; a++) {
                int bb = (a * 8 + gid) * ATP + kb;
                uint32_t vh[2] = {*(const uint32_t*)&SVh[bb], *(const uint32_t*)&SVh[bb + 8]};
                uint32_t vl[2] = {*(const uint32_t*)&SVl[bb], *(const uint32_t*)&SVl[bb + 8]};
                mma16816(o[a], ah, vh);
                mma16816(o[a], ah, vl);
                mma16816(o[a], al, vh);
            }
        }
        __syncthreads();
    }

    // epilogue: normalize + write bf16 hi/lo splits for proj GEMM
    const float inv0 = 1.f / l0, inv1 = 1.f / l1;
    const int gi0 = i0 + war, gi1 = gi0 + 8;
    const size_t ro0 = ((size_t)b * N_ + gi0) * D_ + h * DH_;
    const size_t ro1 = ((size_t)b * N_ + gi1) * D_ + h * DH_;
    #pragma unroll
    for (int a = 0; a < 8; a++) {
        int d = a * 8 + tg * 2;
        if (gi0 < N_) {
            uint32_t hi, lo;
            pksplit(o[a][0] * inv0, o[a][1] * inv0, hi, lo);
            *(uint32_t*)(g_ao0 + ro0 + d) = hi;
            *(uint32_t*)(g_ao1 + ro0 + d) = lo;
        }
        if (gi1 < N_) {
            uint32_t hi, lo;
            pksplit(o[a][2] * inv1, o[a][3] * inv1, hi, lo);
            *(uint32_t*)(g_ao0 + ro1 + d) = hi;
            *(uint32_t*)(g_ao1 + ro1 + d) = lo;
        }
    }
}

// ---------------------------------------------------------------------------
extern "C" void kernel_launch(void* const* d_in, const int* in_sizes, int n_in,
                              void* d_out, int out_size) {
    (void)in_sizes; (void)n_in; (void)out_size;
    const float* x    = (const float*)d_in[0];
    const float* qkvw = (const float*)d_in[1];
    const float* pw   = (const float*)d_in[2];
    const float* pb   = (const float*)d_in[3];
    const float* b1   = (const float*)d_in[4];
    const float* b2   = (const float*)d_in[5];
    const float* b3   = (const float*)d_in[6];
    const int*   map  = (const int*)d_in[7];
    float* out = (float*)d_out;

    cudaFuncSetAttribute(attn_mma, cudaFuncAttributeMaxDynamicSharedMemorySize, ATT_SMEM);
    cudaFuncSetAttribute(gemm_mma<0>, cudaFuncAttributeMaxDynamicSharedMemorySize, GEMM_SMEM);
    cudaFuncSetAttribute(gemm_mma<1>, cudaFuncAttributeMaxDynamicSharedMemorySize, GEMM_SMEM);

    bias_build<<<CDIV(H_ * IPADR * BPAD, 256), 256>>>(b1, b2, b3, map);
    split_k<0><<<CDIV(MR * D_ / 4, 256), 256>>>(x);
    split_k<1><<<CDIV(3 * D_ * D_ / 4, 256), 256>>>(qkvw);
    split_k<2><<<CDIV(D_ * D_ / 4, 256), 256>>>(pw);

    gemm_mma<0><<<dim3(3 * D_ / 128, CDIV(MR, 128)), 256, GEMM_SMEM>>>(nullptr, nullptr);
    vtrans<<<dim3(JP / 64, B_ * H_), 256>>>();
    attn_mma<<<dim3(CDIV(N_, 64), B_ * H_), 128, ATT_SMEM>>>();
    gemm_mma<1><<<dim3(D_ / 128, CDIV(MR, 128)), 256, GEMM_SMEM>>>(pb, out);
}